// round 14
// baseline (speedup 1.0000x reference)
#include <cuda_runtime.h>
#include <cstdint>

#define HH 768
#define WW 768
#define NPIX (HH * WW)

// Offsets (in floats) into the single concatenated output buffer:
//   rendered_vertex_attr [H,W,32,2] -> NPIX*64
//   rendered_frag_attr   [H,W,16,2] -> NPIX*32
//   depth                [H,W,1,2]  -> NPIX*2
//   mask                 [H,W,1,2]  -> NPIX*2
#define OFF_FATTR ((size_t)NPIX * 64)
#define OFF_DEPTH ((size_t)NPIX * 96)
#define OFF_MASK  ((size_t)NPIX * 98)

__device__ int g_fragid_is64;

// frag_id was requested as int64 in the reference, but default-JAX demotes it
// to int32. Detect at runtime: if stored as little-endian int64 with values in
// [0, 500000), every odd 32-bit word of the first 64 entries is zero. If it's
// int32, those words are random triangle ids — all-zero is impossible in
// practice. Deterministic, runs every launch, graph-capturable.
__global__ void detect_dtype_kernel(const unsigned int* __restrict__ p) {
    unsigned int acc = 0;
#pragma unroll
    for (int i = 0; i < 64; i++) acc |= p[2 * i + 1];
    g_fragid_is64 = (acc == 0u) ? 1 : 0;
}

// XLA eager reduce emulation (CONFIRMED bit-exact via output 0): products
// individually rounded, then linear ascending reduce with plain adds.
// Intrinsics are never fmad-contracted by nvcc.
__device__ __forceinline__ float wsum3(float b0, float x0, float b1, float x1,
                                       float b2, float x2) {
    return __fadd_rn(__fadd_rn(__fmul_rn(b0, x0), __fmul_rn(b1, x1)),
                     __fmul_rn(b2, x2));
}

// Candidate (untested — R12 run was an infra failure): adjacent-pairwise
// balanced tree, plain rounds: (m0 + m1) + (m2 + m3).
// This is LLVM's reassociated/balanced form of a 4-term fadd chain and the
// standard 4-wide SIMD horizontal reduction.
__device__ __forceinline__ float dot4_pairwise(float p0, float c0, float p1,
                                               float c1, float p2, float c2,
                                               float p3, float c3) {
    float m0 = __fmul_rn(p0, c0);
    float m1 = __fmul_rn(p1, c1);
    float m2 = __fmul_rn(p2, c2);
    float m3 = __fmul_rn(p3, c3);
    return __fadd_rn(__fadd_rn(m0, m1), __fadd_rn(m2, m3));
}

__global__ __launch_bounds__(256) void render_kernel(
    const float* __restrict__ attr,     // [T,3,32]
    const void*  __restrict__ frag_id,  // [H,W,2] int32 or int64
    const float* __restrict__ mask,     // [H,W,1,2]
    const float* __restrict__ bary,     // [H,W,3,2]
    const float* __restrict__ cam,      // [4,4] (cam_w2c_4x4_T)
    const float* __restrict__ tri,      // [T,3,4]
    const float* __restrict__ fattr,    // [T,16]
    float* __restrict__ out)
{
    // 4 pixels per 256-thread block; 64 threads per pixel; thread = (c, l)
    const int pix = blockIdx.x * 4 + (threadIdx.x >> 6);
    const int t64 = threadIdx.x & 63;
    const int l = t64 & 1;        // layer 0/1 (even/odd lanes)
    const int c = t64 >> 1;       // channel 0..31

    long long id;
    if (g_fragid_is64) id = ((const long long*)frag_id)[pix * 2 + l];
    else               id = ((const int*)frag_id)[pix * 2 + l];

    // barycentrics layout [H,W,3,L]
    const float b0 = __ldg(&bary[(pix * 3 + 0) * 2 + l]);
    const float b1 = __ldg(&bary[(pix * 3 + 1) * 2 + l]);
    const float b2 = __ldg(&bary[(pix * 3 + 2) * 2 + l]);

    // --- rendered_vertex_attr: sum_k bary[k] * attr[id][k][c] ---
    // (bit-exact vs reference as of R9 — do not touch)
    const float* arow = attr + (size_t)id * 96;
    float v = wsum3(b0, __ldg(arow + c),
                    b1, __ldg(arow + 32 + c),
                    b2, __ldg(arow + 64 + c));
    // output [H,W,C,L]: ((pix*32 + c)*2 + l) == pix*64 + t64 -> warp-contiguous
    out[(size_t)pix * 64 + t64] = v;

    const float m = __ldg(&mask[pix * 2 + l]);

    // --- rendered_frag_attr: frag_attr[id][f] * mask, f = c for c<16 ---
    // (bit-exact — do not touch)
    if (c < 16) {
        out[OFF_FATTR + (size_t)pix * 32 + t64] =
            __fmul_rn(__ldg(&fattr[(size_t)id * 16 + c]), m);
    }

    // --- depth + mask passthrough: one lane pair (c==31) per pixel ---
    // global_pos: confirmed weighted-sum form (identical structure to output
    // 0, which is bitwise exact). cam matmul: adjacent-pairwise plain tree
    // (hypothesis under test). div: IEEE div.rn. mask is binary, so the
    // epilogue ops are exact regardless of form.
    if (c == 31) {
        const float* trow = tri + (size_t)id * 12;
        float p[4];
#pragma unroll
        for (int j = 0; j < 4; j++) {
            p[j] = wsum3(b0, __ldg(trow + j),
                         b1, __ldg(trow + 4 + j),
                         b2, __ldg(trow + 8 + j));
        }
        // z = cam_pos[...,2], w = cam_pos[...,3]; M[i,j] = cam[i*4+j]
        float z = dot4_pairwise(p[0], __ldg(cam + 2),  p[1], __ldg(cam + 6),
                                p[2], __ldg(cam + 10), p[3], __ldg(cam + 14));
        float w = dot4_pairwise(p[0], __ldg(cam + 3),  p[1], __ldg(cam + 7),
                                p[2], __ldg(cam + 11), p[3], __ldg(cam + 15));

        float d = __fdiv_rn(z, __fadd_rn(w, 1e-6f));
        float dout = __fadd_rn(__fmul_rn(d, m), __fadd_rn(m, -1.0f));
        out[OFF_DEPTH + (size_t)pix * 2 + l] = dout;
        out[OFF_MASK  + (size_t)pix * 2 + l] = m;
    }
}

extern "C" void kernel_launch(void* const* d_in, const int* in_sizes, int n_in,
                              void* d_out, int out_size) {
    const float* attr    = (const float*)d_in[0];
    const void*  frag_id = d_in[1];
    const float* mask    = (const float*)d_in[2];
    const float* bary    = (const float*)d_in[3];
    const float* cam     = (const float*)d_in[4];
    const float* tri     = (const float*)d_in[5];
    const float* fattr   = (const float*)d_in[6];
    float* out = (float*)d_out;

    detect_dtype_kernel<<<1, 1>>>((const unsigned int*)frag_id);
    render_kernel<<<NPIX / 4, 256>>>(attr, frag_id, mask, bary, cam, tri, fattr, out);
}

// round 15
// speedup vs baseline: 1.7694x; 1.7694x over previous
#include <cuda_runtime.h>
#include <cstdint>

#define HH 768
#define WW 768
#define NPIX (HH * WW)

// Offsets (in floats) into the single concatenated output buffer:
//   rendered_vertex_attr [H,W,32,2] -> NPIX*64
//   rendered_frag_attr   [H,W,16,2] -> NPIX*32
//   depth                [H,W,1,2]  -> NPIX*2
//   mask                 [H,W,1,2]  -> NPIX*2
#define OFF_FATTR ((size_t)NPIX * 64)
#define OFF_DEPTH ((size_t)NPIX * 96)
#define OFF_MASK  ((size_t)NPIX * 98)

__device__ int g_fragid_is64;

// frag_id was requested as int64 in the reference, but default-JAX demotes it
// to int32. Detect at runtime (odd 32-bit words all zero <=> int64).
__global__ void detect_dtype_kernel(const unsigned int* __restrict__ p) {
    unsigned int acc = 0;
#pragma unroll
    for (int i = 0; i < 64; i++) acc |= p[2 * i + 1];
    g_fragid_is64 = (acc == 0u) ? 1 : 0;
}

// CONFIRMED bit-exact (R14, rel_err 0.0): products individually rounded,
// linear ascending reduce with plain adds. Never fmad-contracted.
__device__ __forceinline__ float wsum3(float b0, float x0, float b1, float x1,
                                       float b2, float x2) {
    return __fadd_rn(__fadd_rn(__fmul_rn(b0, x0), __fmul_rn(b1, x1)),
                     __fmul_rn(b2, x2));
}

// CONFIRMED bit-exact (R14): adjacent-pairwise balanced tree (m0+m1)+(m2+m3).
__device__ __forceinline__ float dot4_pairwise(float p0, float c0, float p1,
                                               float c1, float p2, float c2,
                                               float p3, float c3) {
    float m0 = __fmul_rn(p0, c0);
    float m1 = __fmul_rn(p1, c1);
    float m2 = __fmul_rn(p2, c2);
    float m3 = __fmul_rn(p3, c3);
    return __fadd_rn(__fadd_rn(m0, m1), __fadd_rn(m2, m3));
}

__global__ __launch_bounds__(256) void render_kernel(
    const float* __restrict__ attr,     // [T,3,32]
    const void*  __restrict__ frag_id,  // [H,W,2] int32 or int64
    const float* __restrict__ mask,     // [H,W,1,2]
    const float* __restrict__ bary,     // [H,W,3,2]
    const float* __restrict__ cam,      // [4,4] (cam_w2c_4x4_T)
    const float* __restrict__ tri,      // [T,3,4]
    const float* __restrict__ fattr,    // [T,16]
    float* __restrict__ out)
{
    // 16 pixels per 256-thread block; 16 threads per pixel.
    // Thread tc handles channels (2tc, 2tc+1) for BOTH layers.
    const int pix = blockIdx.x * 16 + (threadIdx.x >> 4);
    const int tc  = threadIdx.x & 15;
    const int c0  = tc * 2;

    // Both layer ids, vector-loaded once per thread.
    long long id0, id1;
    if (g_fragid_is64) {
        longlong2 ii = __ldg(&((const longlong2*)frag_id)[pix]);
        id0 = ii.x; id1 = ii.y;
    } else {
        int2 ii = __ldg(&((const int2*)frag_id)[pix]);
        id0 = ii.x; id1 = ii.y;
    }

    // barycentrics [H,W,3,2]: three float2 loads -> b[k].x = layer0, .y = layer1
    const float2* bp = (const float2*)(bary + (size_t)pix * 6);
    const float2 bk0 = __ldg(bp + 0);
    const float2 bk1 = __ldg(bp + 1);
    const float2 bk2 = __ldg(bp + 2);

    const float2 m2v = __ldg((const float2*)(mask + (size_t)pix * 2));

    // --- rendered_vertex_attr: float2 gathers per corner per layer ---
    const float* a0row = attr + (size_t)id0 * 96 + c0;
    const float* a1row = attr + (size_t)id1 * 96 + c0;
    float2 x0 = __ldg((const float2*)(a0row));
    float2 x1 = __ldg((const float2*)(a0row + 32));
    float2 x2 = __ldg((const float2*)(a0row + 64));
    float2 y0 = __ldg((const float2*)(a1row));
    float2 y1 = __ldg((const float2*)(a1row + 32));
    float2 y2 = __ldg((const float2*)(a1row + 64));

    float4 vout;
    vout.x = wsum3(bk0.x, x0.x, bk1.x, x1.x, bk2.x, x2.x);  // (c0,   l=0)
    vout.y = wsum3(bk0.y, y0.x, bk1.y, y1.x, bk2.y, y2.x);  // (c0,   l=1)
    vout.z = wsum3(bk0.x, x0.y, bk1.x, x1.y, bk2.x, x2.y);  // (c0+1, l=0)
    vout.w = wsum3(bk0.y, y0.y, bk1.y, y1.y, bk2.y, y2.y);  // (c0+1, l=1)
    // out [H,W,C,L]: element (pix, c, l) at pix*64 + c*2 + l; float4 covers
    // (c0,0),(c0,1),(c0+1,0),(c0+1,1) = offsets pix*64 + tc*4 .. +3.
    ((float4*)(out + (size_t)pix * 64))[tc] = vout;

    // --- rendered_frag_attr: threads tc<8 cover channels (2tc,2tc+1) x 2 ---
    if (tc < 8) {
        float2 f0 = __ldg((const float2*)(fattr + (size_t)id0 * 16 + c0));
        float2 f1 = __ldg((const float2*)(fattr + (size_t)id1 * 16 + c0));
        float4 fo;
        fo.x = __fmul_rn(f0.x, m2v.x);
        fo.y = __fmul_rn(f1.x, m2v.y);
        fo.z = __fmul_rn(f0.y, m2v.x);
        fo.w = __fmul_rn(f1.y, m2v.y);
        ((float4*)(out + OFF_FATTR + (size_t)pix * 32))[tc] = fo;
    }

    // --- depth + mask: tc==8 -> layer 0, tc==9 -> layer 1 ---
    if ((tc & 14) == 8) {           // tc == 8 or 9
        const int l = tc & 1;
        const long long id = l ? id1 : id0;
        const float b0 = l ? bk0.y : bk0.x;
        const float b1 = l ? bk1.y : bk1.x;
        const float b2 = l ? bk2.y : bk2.x;
        const float m  = l ? m2v.y : m2v.x;

        const float4* trow = (const float4*)(tri + (size_t)id * 12);
        const float4 t0 = __ldg(trow + 0);
        const float4 t1 = __ldg(trow + 1);
        const float4 t2 = __ldg(trow + 2);

        const float p0 = wsum3(b0, t0.x, b1, t1.x, b2, t2.x);
        const float p1 = wsum3(b0, t0.y, b1, t1.y, b2, t2.y);
        const float p2 = wsum3(b0, t0.z, b1, t1.z, b2, t2.z);
        const float p3 = wsum3(b0, t0.w, b1, t1.w, b2, t2.w);

        // z = cam_pos[...,2], w = cam_pos[...,3]; M[i,j] = cam[i*4+j]
        float z = dot4_pairwise(p0, __ldg(cam + 2),  p1, __ldg(cam + 6),
                                p2, __ldg(cam + 10), p3, __ldg(cam + 14));
        float w = dot4_pairwise(p0, __ldg(cam + 3),  p1, __ldg(cam + 7),
                                p2, __ldg(cam + 11), p3, __ldg(cam + 15));

        float d = __fdiv_rn(z, __fadd_rn(w, 1e-6f));
        float dout = __fadd_rn(__fmul_rn(d, m), __fadd_rn(m, -1.0f));
        out[OFF_DEPTH + (size_t)pix * 2 + l] = dout;
        out[OFF_MASK  + (size_t)pix * 2 + l] = m;
    }
}

extern "C" void kernel_launch(void* const* d_in, const int* in_sizes, int n_in,
                              void* d_out, int out_size) {
    const float* attr    = (const float*)d_in[0];
    const void*  frag_id = d_in[1];
    const float* mask    = (const float*)d_in[2];
    const float* bary    = (const float*)d_in[3];
    const float* cam     = (const float*)d_in[4];
    const float* tri     = (const float*)d_in[5];
    const float* fattr   = (const float*)d_in[6];
    float* out = (float*)d_out;

    detect_dtype_kernel<<<1, 1>>>((const unsigned int*)frag_id);
    render_kernel<<<NPIX / 16, 256>>>(attr, frag_id, mask, bary, cam, tri, fattr, out);
}

// round 16
// speedup vs baseline: 1.8932x; 1.0700x over previous
#include <cuda_runtime.h>
#include <cstdint>

#define HH 768
#define WW 768
#define NPIX (HH * WW)

// Offsets (in floats) into the single concatenated output buffer:
//   rendered_vertex_attr [H,W,32,2] -> NPIX*64
//   rendered_frag_attr   [H,W,16,2] -> NPIX*32
//   depth                [H,W,1,2]  -> NPIX*2
//   mask                 [H,W,1,2]  -> NPIX*2
#define OFF_FATTR ((size_t)NPIX * 64)
#define OFF_DEPTH ((size_t)NPIX * 96)
#define OFF_MASK  ((size_t)NPIX * 98)

__device__ int g_fragid_is64;

// frag_id was requested as int64 in the reference, but default-JAX demotes it
// to int32. Detect at runtime (odd 32-bit words all zero <=> int64).
__global__ void detect_dtype_kernel(const unsigned int* __restrict__ p) {
    unsigned int acc = 0;
#pragma unroll
    for (int i = 0; i < 64; i++) acc |= p[2 * i + 1];
    g_fragid_is64 = (acc == 0u) ? 1 : 0;
}

// CONFIRMED bit-exact (R14, rel_err 0.0): products individually rounded,
// linear ascending reduce with plain adds. Never fmad-contracted.
__device__ __forceinline__ float wsum3(float b0, float x0, float b1, float x1,
                                       float b2, float x2) {
    return __fadd_rn(__fadd_rn(__fmul_rn(b0, x0), __fmul_rn(b1, x1)),
                     __fmul_rn(b2, x2));
}

// CONFIRMED bit-exact (R14): adjacent-pairwise balanced tree (m0+m1)+(m2+m3).
__device__ __forceinline__ float dot4_pairwise(float p0, float c0, float p1,
                                               float c1, float p2, float c2,
                                               float p3, float c3) {
    float m0 = __fmul_rn(p0, c0);
    float m1 = __fmul_rn(p1, c1);
    float m2 = __fmul_rn(p2, c2);
    float m3 = __fmul_rn(p3, c3);
    return __fadd_rn(__fadd_rn(m0, m1), __fadd_rn(m2, m3));
}

__global__ __launch_bounds__(256) void render_kernel(
    const float* __restrict__ attr,     // [T,3,32]
    const void*  __restrict__ frag_id,  // [H,W,2] int32 or int64
    const float* __restrict__ mask,     // [H,W,1,2]
    const float* __restrict__ bary,     // [H,W,3,2]
    const float* __restrict__ cam,      // [4,4] (cam_w2c_4x4_T)
    const float* __restrict__ tri,      // [T,3,4]
    const float* __restrict__ fattr,    // [T,16]
    float* __restrict__ out)
{
    // 32 pixels per 256-thread block; 8 threads per pixel.
    // Thread tc handles channels c0..c0+3 (c0 = 4*tc) for BOTH layers.
    const int pix = blockIdx.x * 32 + (threadIdx.x >> 3);
    const int tc  = threadIdx.x & 7;
    const int c0  = tc * 4;

    // Both layer ids; per-pixel streams are read-once -> evict-first (__ldcs).
    long long id0, id1;
    if (g_fragid_is64) {
        longlong2 ii = __ldcs(&((const longlong2*)frag_id)[pix]);
        id0 = ii.x; id1 = ii.y;
    } else {
        int2 ii = __ldcs(&((const int2*)frag_id)[pix]);
        id0 = ii.x; id1 = ii.y;
    }

    // barycentrics [H,W,3,2]: b[k].x = layer0, .y = layer1
    const float2* bp = (const float2*)(bary + (size_t)pix * 6);
    const float2 bk0 = __ldcs(bp + 0);
    const float2 bk1 = __ldcs(bp + 1);
    const float2 bk2 = __ldcs(bp + 2);

    const float2 m2v = __ldcs((const float2*)(mask + (size_t)pix * 2));

    // --- rendered_vertex_attr: float4 gathers per corner per layer ---
    // attr row base is 384B-aligned; +c0*4B with c0%4==0 -> 16B aligned.
    // Gather tables have L2 reuse -> default caching (__ldg).
    const float* a0row = attr + (size_t)id0 * 96 + c0;
    const float* a1row = attr + (size_t)id1 * 96 + c0;
    float4 x0 = __ldg((const float4*)(a0row));
    float4 x1 = __ldg((const float4*)(a0row + 32));
    float4 x2 = __ldg((const float4*)(a0row + 64));
    float4 y0 = __ldg((const float4*)(a1row));
    float4 y1 = __ldg((const float4*)(a1row + 32));
    float4 y2 = __ldg((const float4*)(a1row + 64));

    // out [H,W,C,L]: element (pix, c, l) at pix*64 + c*2 + l.
    // Thread covers floats pix*64 + c0*2 .. c0*2+7 -> two float4 stores.
    float4 v0, v1;
    v0.x = wsum3(bk0.x, x0.x, bk1.x, x1.x, bk2.x, x2.x);  // (c0,   0)
    v0.y = wsum3(bk0.y, y0.x, bk1.y, y1.x, bk2.y, y2.x);  // (c0,   1)
    v0.z = wsum3(bk0.x, x0.y, bk1.x, x1.y, bk2.x, x2.y);  // (c0+1, 0)
    v0.w = wsum3(bk0.y, y0.y, bk1.y, y1.y, bk2.y, y2.y);  // (c0+1, 1)
    v1.x = wsum3(bk0.x, x0.z, bk1.x, x1.z, bk2.x, x2.z);  // (c0+2, 0)
    v1.y = wsum3(bk0.y, y0.z, bk1.y, y1.z, bk2.y, y2.z);  // (c0+2, 1)
    v1.z = wsum3(bk0.x, x0.w, bk1.x, x1.w, bk2.x, x2.w);  // (c0+3, 0)
    v1.w = wsum3(bk0.y, y0.w, bk1.y, y1.w, bk2.y, y2.w);  // (c0+3, 1)
    float4* vo = (float4*)(out + (size_t)pix * 64) + tc * 2;
    __stcs(vo + 0, v0);       // streaming: keep L2 for the gather tables
    __stcs(vo + 1, v1);

    // --- rendered_frag_attr: tc<4 cover channels c0..c0+3, both layers ---
    if (tc < 4) {
        float4 f0 = __ldg((const float4*)(fattr + (size_t)id0 * 16 + c0));
        float4 f1 = __ldg((const float4*)(fattr + (size_t)id1 * 16 + c0));
        float4 g0, g1;
        g0.x = __fmul_rn(f0.x, m2v.x);
        g0.y = __fmul_rn(f1.x, m2v.y);
        g0.z = __fmul_rn(f0.y, m2v.x);
        g0.w = __fmul_rn(f1.y, m2v.y);
        g1.x = __fmul_rn(f0.z, m2v.x);
        g1.y = __fmul_rn(f1.z, m2v.y);
        g1.z = __fmul_rn(f0.w, m2v.x);
        g1.w = __fmul_rn(f1.w, m2v.y);
        float4* fo = (float4*)(out + OFF_FATTR + (size_t)pix * 32) + tc * 2;
        __stcs(fo + 0, g0);
        __stcs(fo + 1, g1);
    }

    // --- depth + mask: tc==4 -> layer 0, tc==5 -> layer 1 ---
    if ((tc & 6) == 4) {            // tc == 4 or 5
        const int l = tc & 1;
        const long long id = l ? id1 : id0;
        const float b0 = l ? bk0.y : bk0.x;
        const float b1 = l ? bk1.y : bk1.x;
        const float b2 = l ? bk2.y : bk2.x;
        const float m  = l ? m2v.y : m2v.x;

        const float4* trow = (const float4*)(tri + (size_t)id * 12);
        const float4 t0 = __ldg(trow + 0);
        const float4 t1 = __ldg(trow + 1);
        const float4 t2 = __ldg(trow + 2);

        const float p0 = wsum3(b0, t0.x, b1, t1.x, b2, t2.x);
        const float p1 = wsum3(b0, t0.y, b1, t1.y, b2, t2.y);
        const float p2 = wsum3(b0, t0.z, b1, t1.z, b2, t2.z);
        const float p3 = wsum3(b0, t0.w, b1, t1.w, b2, t2.w);

        // z = cam_pos[...,2], w = cam_pos[...,3]; M[i,j] = cam[i*4+j]
        float z = dot4_pairwise(p0, __ldg(cam + 2),  p1, __ldg(cam + 6),
                                p2, __ldg(cam + 10), p3, __ldg(cam + 14));
        float w = dot4_pairwise(p0, __ldg(cam + 3),  p1, __ldg(cam + 7),
                                p2, __ldg(cam + 11), p3, __ldg(cam + 15));

        float d = __fdiv_rn(z, __fadd_rn(w, 1e-6f));
        float dout = __fadd_rn(__fmul_rn(d, m), __fadd_rn(m, -1.0f));
        __stcs(out + OFF_DEPTH + (size_t)pix * 2 + l, dout);
        __stcs(out + OFF_MASK  + (size_t)pix * 2 + l, m);
    }
}

extern "C" void kernel_launch(void* const* d_in, const int* in_sizes, int n_in,
                              void* d_out, int out_size) {
    const float* attr    = (const float*)d_in[0];
    const void*  frag_id = d_in[1];
    const float* mask    = (const float*)d_in[2];
    const float* bary    = (const float*)d_in[3];
    const float* cam     = (const float*)d_in[4];
    const float* tri     = (const float*)d_in[5];
    const float* fattr   = (const float*)d_in[6];
    float* out = (float*)d_out;

    detect_dtype_kernel<<<1, 1>>>((const unsigned int*)frag_id);
    render_kernel<<<NPIX / 32, 256>>>(attr, frag_id, mask, bary, cam, tri, fattr, out);
}

// round 17
// speedup vs baseline: 1.9010x; 1.0041x over previous
#include <cuda_runtime.h>
#include <cstdint>

#define HH 768
#define WW 768
#define NPIX (HH * WW)

// Offsets (in floats) into the single concatenated output buffer:
//   rendered_vertex_attr [H,W,32,2] -> NPIX*64
//   rendered_frag_attr   [H,W,16,2] -> NPIX*32
//   depth                [H,W,1,2]  -> NPIX*2
//   mask                 [H,W,1,2]  -> NPIX*2
#define OFF_FATTR ((size_t)NPIX * 64)
#define OFF_DEPTH ((size_t)NPIX * 96)
#define OFF_MASK  ((size_t)NPIX * 98)

// CONFIRMED bit-exact (R14, rel_err 0.0): products individually rounded,
// linear ascending reduce with plain adds. Never fmad-contracted.
__device__ __forceinline__ float wsum3(float b0, float x0, float b1, float x1,
                                       float b2, float x2) {
    return __fadd_rn(__fadd_rn(__fmul_rn(b0, x0), __fmul_rn(b1, x1)),
                     __fmul_rn(b2, x2));
}

// CONFIRMED bit-exact (R14): adjacent-pairwise balanced tree (m0+m1)+(m2+m3).
__device__ __forceinline__ float dot4_pairwise(float p0, float c0, float p1,
                                               float c1, float p2, float c2,
                                               float p3, float c3) {
    float m0 = __fmul_rn(p0, c0);
    float m1 = __fmul_rn(p1, c1);
    float m2 = __fmul_rn(p2, c2);
    float m3 = __fmul_rn(p3, c3);
    return __fadd_rn(__fadd_rn(m0, m1), __fadd_rn(m2, m3));
}

__global__ __launch_bounds__(256, 8) void render_kernel(
    const float* __restrict__ attr,     // [T,3,32]
    const void*  __restrict__ frag_id,  // [H,W,2] int32 or int64
    const float* __restrict__ mask,     // [H,W,1,2]
    const float* __restrict__ bary,     // [H,W,3,2]
    const float* __restrict__ cam,      // [4,4] (cam_w2c_4x4_T)
    const float* __restrict__ tri,      // [T,3,4]
    const float* __restrict__ fattr,    // [T,16]
    float* __restrict__ out)
{
    // Per-block frag_id dtype detection (int64 iff all odd 32-bit words of the
    // first 64 entries are zero; ids are random in [0,500000) so an int32
    // buffer cannot produce 64 zero odd-words). L2-broadcast hits, ~free.
    __shared__ int s_is64;
    if (threadIdx.x == 0) {
        const unsigned int* p = (const unsigned int*)frag_id;
        unsigned int acc = 0;
#pragma unroll
        for (int i = 0; i < 64; i++) acc |= p[2 * i + 1];
        s_is64 = (acc == 0u) ? 1 : 0;
    }
    __syncthreads();

    // 32 pixels per 256-thread block; 8 threads per pixel.
    // Thread tc handles channels c0..c0+3 (c0 = 4*tc) for BOTH layers.
    const int pix = blockIdx.x * 32 + (threadIdx.x >> 3);
    const int tc  = threadIdx.x & 7;
    const int c0  = tc * 4;

    // Both layer ids; per-pixel streams are read-once -> evict-first (__ldcs).
    long long id0, id1;
    if (s_is64) {
        longlong2 ii = __ldcs(&((const longlong2*)frag_id)[pix]);
        id0 = ii.x; id1 = ii.y;
    } else {
        int2 ii = __ldcs(&((const int2*)frag_id)[pix]);
        id0 = ii.x; id1 = ii.y;
    }

    // barycentrics [H,W,3,2]: b[k].x = layer0, .y = layer1
    const float2* bp = (const float2*)(bary + (size_t)pix * 6);
    const float2 bk0 = __ldcs(bp + 0);
    const float2 bk1 = __ldcs(bp + 1);
    const float2 bk2 = __ldcs(bp + 2);

    const float2 m2v = __ldcs((const float2*)(mask + (size_t)pix * 2));

    // --- rendered_vertex_attr: float4 gathers per corner per layer ---
    // Random rows -> no L1 reuse: L2-only (__ldcg) to avoid L1 churn.
    const float* a0row = attr + (size_t)id0 * 96 + c0;
    const float* a1row = attr + (size_t)id1 * 96 + c0;
    float4 x0 = __ldcg((const float4*)(a0row));
    float4 x1 = __ldcg((const float4*)(a0row + 32));
    float4 x2 = __ldcg((const float4*)(a0row + 64));
    float4 y0 = __ldcg((const float4*)(a1row));
    float4 y1 = __ldcg((const float4*)(a1row + 32));
    float4 y2 = __ldcg((const float4*)(a1row + 64));

    // out [H,W,C,L]: element (pix, c, l) at pix*64 + c*2 + l.
    // Thread covers floats pix*64 + c0*2 .. c0*2+7 -> two float4 stores.
    float4 v0, v1;
    v0.x = wsum3(bk0.x, x0.x, bk1.x, x1.x, bk2.x, x2.x);  // (c0,   0)
    v0.y = wsum3(bk0.y, y0.x, bk1.y, y1.x, bk2.y, y2.x);  // (c0,   1)
    v0.z = wsum3(bk0.x, x0.y, bk1.x, x1.y, bk2.x, x2.y);  // (c0+1, 0)
    v0.w = wsum3(bk0.y, y0.y, bk1.y, y1.y, bk2.y, y2.y);  // (c0+1, 1)
    v1.x = wsum3(bk0.x, x0.z, bk1.x, x1.z, bk2.x, x2.z);  // (c0+2, 0)
    v1.y = wsum3(bk0.y, y0.z, bk1.y, y1.z, bk2.y, y2.z);  // (c0+2, 1)
    v1.z = wsum3(bk0.x, x0.w, bk1.x, x1.w, bk2.x, x2.w);  // (c0+3, 0)
    v1.w = wsum3(bk0.y, y0.w, bk1.y, y1.w, bk2.y, y2.w);  // (c0+3, 1)
    float4* vo = (float4*)(out + (size_t)pix * 64) + tc * 2;
    __stcs(vo + 0, v0);       // streaming: keep L2 for the gather tables
    __stcs(vo + 1, v1);

    // --- rendered_frag_attr: tc<4 cover channels c0..c0+3, both layers ---
    if (tc < 4) {
        float4 f0 = __ldcg((const float4*)(fattr + (size_t)id0 * 16 + c0));
        float4 f1 = __ldcg((const float4*)(fattr + (size_t)id1 * 16 + c0));
        float4 g0, g1;
        g0.x = __fmul_rn(f0.x, m2v.x);
        g0.y = __fmul_rn(f1.x, m2v.y);
        g0.z = __fmul_rn(f0.y, m2v.x);
        g0.w = __fmul_rn(f1.y, m2v.y);
        g1.x = __fmul_rn(f0.z, m2v.x);
        g1.y = __fmul_rn(f1.z, m2v.y);
        g1.z = __fmul_rn(f0.w, m2v.x);
        g1.w = __fmul_rn(f1.w, m2v.y);
        float4* fo = (float4*)(out + OFF_FATTR + (size_t)pix * 32) + tc * 2;
        __stcs(fo + 0, g0);
        __stcs(fo + 1, g1);
    }

    // --- depth + mask: tc==4 -> layer 0, tc==5 -> layer 1 ---
    if ((tc & 6) == 4) {            // tc == 4 or 5
        const int l = tc & 1;
        const long long id = l ? id1 : id0;
        const float b0 = l ? bk0.y : bk0.x;
        const float b1 = l ? bk1.y : bk1.x;
        const float b2 = l ? bk2.y : bk2.x;
        const float m  = l ? m2v.y : m2v.x;

        const float4* trow = (const float4*)(tri + (size_t)id * 12);
        const float4 t0 = __ldcg(trow + 0);
        const float4 t1 = __ldcg(trow + 1);
        const float4 t2 = __ldcg(trow + 2);

        const float p0 = wsum3(b0, t0.x, b1, t1.x, b2, t2.x);
        const float p1 = wsum3(b0, t0.y, b1, t1.y, b2, t2.y);
        const float p2 = wsum3(b0, t0.z, b1, t1.z, b2, t2.z);
        const float p3 = wsum3(b0, t0.w, b1, t1.w, b2, t2.w);

        // z = cam_pos[...,2], w = cam_pos[...,3]; M[i,j] = cam[i*4+j]
        float z = dot4_pairwise(p0, __ldg(cam + 2),  p1, __ldg(cam + 6),
                                p2, __ldg(cam + 10), p3, __ldg(cam + 14));
        float w = dot4_pairwise(p0, __ldg(cam + 3),  p1, __ldg(cam + 7),
                                p2, __ldg(cam + 11), p3, __ldg(cam + 15));

        float d = __fdiv_rn(z, __fadd_rn(w, 1e-6f));
        float dout = __fadd_rn(__fmul_rn(d, m), __fadd_rn(m, -1.0f));
        __stcs(out + OFF_DEPTH + (size_t)pix * 2 + l, dout);
        __stcs(out + OFF_MASK  + (size_t)pix * 2 + l, m);
    }
}

extern "C" void kernel_launch(void* const* d_in, const int* in_sizes, int n_in,
                              void* d_out, int out_size) {
    const float* attr    = (const float*)d_in[0];
    const void*  frag_id = d_in[1];
    const float* mask    = (const float*)d_in[2];
    const float* bary    = (const float*)d_in[3];
    const float* cam     = (const float*)d_in[4];
    const float* tri     = (const float*)d_in[5];
    const float* fattr   = (const float*)d_in[6];
    float* out = (float*)d_out;

    render_kernel<<<NPIX / 32, 256>>>(attr, frag_id, mask, bary, cam, tri, fattr, out);
}